// round 4
// baseline (speedup 1.0000x reference)
#include <cuda_runtime.h>
#include <cstdint>

// ============================================================================
// FourierKARTLayer, f-split co-block version.
//   W2[(kk*128+q), d] = A*cos(Bp) (kk<6, sin part) / A*sin(Bp) (kk>=6, cos part)
//   grid = 512: block (tile = bx>>1, h = bx&1); h=0 -> sin rows, h=1 -> cos rows
//   Co-blocks each compute angles+sincos for their 8 tokens, then GEMM2 over
//   their 768-feature half; partial V combined via RED.ADD.F32.
// ============================================================================

#define D_INF   256
#define D_OUTF  64
#define NQ      128
#define NK      6
#define NTOK    2048
#define TPB     256
#define TOKB    8
#define NFEAT   1536
#define FHALF   768

__device__ float g_WcT[D_INF * NQ];     // [i][q]
__device__ float g_W2[NFEAT * D_OUTF];  // [f][d]

using u64 = unsigned long long;

__device__ __forceinline__ u64 pack2(float x, float y) {
    u64 r; asm("mov.b64 %0, {%1, %2};" : "=l"(r) : "f"(x), "f"(y)); return r;
}
__device__ __forceinline__ u64 fma2(u64 a, u64 b, u64 c) {
    u64 d; asm("fma.rn.f32x2 %0, %1, %2, %3;" : "=l"(d) : "l"(a), "l"(b), "l"(c)); return d;
}
__device__ __forceinline__ float2 unpack2(u64 a) {
    float2 f; asm("mov.b64 {%0, %1}, %2;" : "=f"(f.x), "=f"(f.y) : "l"(a)); return f;
}
__device__ __forceinline__ u64 add2(u64 a, u64 b) {
    u64 d; asm("add.rn.f32x2 %0, %1, %2;" : "=l"(d) : "l"(a), "l"(b)); return d;
}

// ----------------------------------------------------------------------------
// Prep: fold Bp into W2; transpose Wc; zero V (for the RED.ADD combine).
// grid 512 x 256 = 131072 threads.
// ----------------------------------------------------------------------------
__global__ void prep_kernel(const float* __restrict__ Wc_w,
                            const float* __restrict__ A,
                            const float* __restrict__ Bp,
                            float* __restrict__ V) {
    int n = blockIdx.x * blockDim.x + threadIdx.x;
    V[n] = 0.f;                                  // 131072 = NTOK * D_OUTF
    if (n < NFEAT * D_OUTF) {
        int d  = n & (D_OUTF - 1);
        int f  = n >> 6;
        int q  = f & (NQ - 1);
        int kk = f >> 7;                         // 0..11
        int k  = (kk >= NK) ? (kk - NK) : kk;    // 0..5
        int src = (d * NQ + q) * NK + k;
        float a  = A[src];
        float bp = Bp[src];
        float nr = rintf(bp * 0.15915494309189535f);
        float br = fmaf(nr, -6.283185307179586f, bp);
        float sb, cb;
        __sincosf(br, &sb, &cb);
        g_W2[n] = (kk < NK) ? (a * cb) : (a * sb);
    }
    if (n < D_INF * NQ) {
        int q = n & (NQ - 1);
        int i = n >> 7;
        g_WcT[n] = Wc_w[q * D_INF + i];
    }
}

// ----------------------------------------------------------------------------
// Main: 512 blocks (256 tiles x 2 f-halves), 256 threads, 4 CTAs/SM.
// smem 56KB: region0 [0,32K) = Xs / E / R (aliased); region1 [32K,56K) = Fs.
// ----------------------------------------------------------------------------
__global__ void __launch_bounds__(TPB, 4) main_kernel(
    const float* __restrict__ X0,
    const float* __restrict__ t,
    const float* __restrict__ Wc_b,
    const float* __restrict__ w,
    float* __restrict__ V) {

    extern __shared__ float smem[];
    float* Xs = smem;                  // [256 i][8 tok]              (region0)
    u64*   E  = (u64*)smem;            // [16 slot][8 ih][32 qg]      (region0)
    u64*   R  = (u64*)smem;            // [16 k][16 swz-col x 16 fs]  (region0)
    float* Fs = smem + 8192;           // [768 f_local][8 tok]        (region1)

    const int tid  = threadIdx.x;
    const int tile = blockIdx.x >> 1;
    const int h    = blockIdx.x & 1;   // 0 = sin rows, 1 = cos rows
    const int g0   = tile * TOKB;
    const float tb = t[g0 >> 10];

    // ---- Phase A: load + transpose X (8 tok x 256 i) --------------------
    {
        int tok = tid >> 5;
        int seg = tid & 31;
        const float4* src = (const float4*)(X0 + (size_t)(g0 + tok) * D_INF + seg * 8);
        float4 v0 = src[0];
        float4 v1 = src[1];
        int i0 = seg * 8;
        Xs[(i0 + 0) * TOKB + tok] = v0.x;
        Xs[(i0 + 1) * TOKB + tok] = v0.y;
        Xs[(i0 + 2) * TOKB + tok] = v0.z;
        Xs[(i0 + 3) * TOKB + tok] = v0.w;
        Xs[(i0 + 4) * TOKB + tok] = v1.x;
        Xs[(i0 + 5) * TOKB + tok] = v1.y;
        Xs[(i0 + 6) * TOKB + tok] = v1.z;
        Xs[(i0 + 7) * TOKB + tok] = v1.w;
    }
    __syncthreads();

    // ---- Phase B1: GEMM1 accumulate (thread = ih x qg, 4q x 8tok) -------
    {
        const int ih = tid >> 5;       // i chunk of 32
        const int qg = tid & 31;       // 4 q's
        u64 acc[16];                   // [qi][pair]
        #pragma unroll
        for (int k = 0; k < 16; k++) acc[k] = 0ULL;

        #pragma unroll 4
        for (int s = 0; s < 32; s++) {
            int i = ih * 32 + s;
            ulonglong2 x01 = *(const ulonglong2*)(Xs + i * TOKB);
            ulonglong2 x23 = *(const ulonglong2*)(Xs + i * TOKB + 4);
            float4 wv = __ldg((const float4*)(g_WcT + i * NQ + qg * 4));
            float wa[4] = {wv.x, wv.y, wv.z, wv.w};
            u64 xp[4] = {x01.x, x01.y, x23.x, x23.y};
            #pragma unroll
            for (int qi = 0; qi < 4; qi++) {
                u64 wd = pack2(wa[qi], wa[qi]);
                #pragma unroll
                for (int p = 0; p < 4; p++)
                    acc[qi * 4 + p] = fma2(xp[p], wd, acc[qi * 4 + p]);
            }
        }
        __syncthreads();               // X reads done; E aliases region0

        #pragma unroll
        for (int qi = 0; qi < 4; qi++)
            #pragma unroll
            for (int p = 0; p < 4; p++)
                E[(qi * 4 + p) * 256 + ih * 32 + qg] = acc[qi * 4 + p];
    }
    __syncthreads();

    // ---- Phase B2: reduce over ih, sincos, store F half -----------------
    {
        const int q  = tid & (NQ - 1);
        const int th = tid >> 7;        // tokens th*4 .. th*4+3
        const int qg = q >> 2;
        const int s0slot = (q & 3) * 4 + th * 2;
        u64 s0 = 0ULL, s1 = 0ULL;
        #pragma unroll
        for (int j = 0; j < 8; j++) {
            s0 = add2(s0, E[s0slot * 256 + j * 32 + qg]);
            s1 = add2(s1, E[(s0slot + 1) * 256 + j * 32 + qg]);
        }
        float init = fmaf(w[q], tb, Wc_b[q]);
        u64 bi = pack2(init, init);
        s0 = add2(s0, bi);
        s1 = add2(s1, bi);
        float2 a01 = unpack2(s0);
        float2 a23 = unpack2(s1);
        float ang[4] = {a01.x, a01.y, a23.x, a23.y};
        __syncthreads();                // E reads done

        float sv[4], cv[4], sk[4], ck[4];
        #pragma unroll
        for (int j = 0; j < 4; j++) {
            float nr = rintf(ang[j] * 0.15915494309189535f);
            float ar = fmaf(nr, -6.283185307179586f, ang[j]);
            __sincosf(ar, &sv[j], &cv[j]);
            sk[j] = sv[j]; ck[j] = cv[j];
        }
        float* base = Fs + q * TOKB + th * 4;
        #pragma unroll
        for (int k = 0; k < NK; k++) {
            *(float4*)(base + (k * NQ) * TOKB) =
                h ? make_float4(ck[0], ck[1], ck[2], ck[3])
                  : make_float4(sk[0], sk[1], sk[2], sk[3]);
            #pragma unroll
            for (int j = 0; j < 4; j++) {
                float ns = fmaf(sk[j], cv[j], ck[j] * sv[j]);
                float nc = fmaf(ck[j], cv[j], -sk[j] * sv[j]);
                sk[j] = ns; ck[j] = nc;
            }
        }
    }
    __syncthreads();

    // ---- Phase C: GEMM2 over 768-feature half, tile 8tok x 4d -----------
    const int fs = tid >> 4;     // 0..15, f_local = j*16 + fs
    const int dg = tid & 15;     // d = dg*4 + dd
    u64 acc2[16];                // [p][dd]
    #pragma unroll
    for (int k = 0; k < 16; k++) acc2[k] = 0ULL;

    const float* w2base = g_W2 + (size_t)h * FHALF * D_OUTF + dg * 4;
    #pragma unroll 4
    for (int j = 0; j < FHALF / 16; j++) {
        int fl = j * 16 + fs;
        const float* frow = Fs + fl * TOKB;
        ulonglong2 f01 = *(const ulonglong2*)frow;
        ulonglong2 f23 = *(const ulonglong2*)(frow + 4);
        float4 wv = __ldg((const float4*)(w2base + fl * D_OUTF));
        u64 fp[4] = {f01.x, f01.y, f23.x, f23.y};
        float wa[4] = {wv.x, wv.y, wv.z, wv.w};
        #pragma unroll
        for (int dd = 0; dd < 4; dd++) {
            u64 wd = pack2(wa[dd], wa[dd]);
            #pragma unroll
            for (int p = 0; p < 4; p++)
                acc2[p * 4 + dd] = fma2(fp[p], wd, acc2[p * 4 + dd]);
        }
    }

    // ---- Reduce 16 f-slices (swizzled, conflict-light) ------------------
    __syncthreads();                   // Fs reads done; R aliases region0
    #pragma unroll
    for (int k = 0; k < 16; k++)
        R[k * 256 + fs * 16 + ((dg + 5 * k) & 15)] = acc2[k];
    __syncthreads();

    {
        int p = tid >> 6;              // token pair 0..3
        int d = tid & 63;
        int k = p * 4 + (d & 3);
        int col = ((d >> 2) + 5 * k) & 15;
        u64 s = 0ULL;
        #pragma unroll
        for (int j = 0; j < 16; j++)
            s = add2(s, R[k * 256 + j * 16 + col]);
        float2 v = unpack2(s);
        float* vp = V + (size_t)(g0 + 2 * p) * D_OUTF + d;
        atomicAdd(vp, v.x);
        atomicAdd(vp + D_OUTF, v.y);
    }
}

// ----------------------------------------------------------------------------
extern "C" void kernel_launch(void* const* d_in, const int* in_sizes, int n_in,
                              void* d_out, int out_size) {
    const float* X0   = (const float*)d_in[0];
    const float* t    = (const float*)d_in[1];
    const float* Wc_w = (const float*)d_in[2];
    const float* Wc_b = (const float*)d_in[3];
    const float* w    = (const float*)d_in[4];
    const float* A    = (const float*)d_in[5];
    const float* Bp   = (const float*)d_in[6];
    float* V = (float*)d_out;

    const int smem_bytes = 57344;      // 32KB region0 + 24KB Fs
    cudaFuncSetAttribute(main_kernel, cudaFuncAttributeMaxDynamicSharedMemorySize, smem_bytes);

    prep_kernel<<<512, 256>>>(Wc_w, A, Bp, V);
    main_kernel<<<512, TPB, smem_bytes>>>(X0, t, Wc_b, w, V);
}

// round 5
// speedup vs baseline: 1.0559x; 1.0559x over previous
#include <cuda_runtime.h>
#include <cstdint>

// ============================================================================
// FourierKARTLayer, 3-kernel version:
//   K0 prep:   W2 = A*cos(Bp)/A*sin(Bp) fold, WcT transpose, zero V
//   K1 angles: angle[tok][q] = X0@WcT + Wc_b + w*t      (computed ONCE)
//   K2 main:   per (token-tile, f-half): sincos+harmonics -> F half (smem),
//              V += F @ W2_half   (RED.ADD combine of the two halves)
// ============================================================================

#define D_INF   256
#define D_OUTF  64
#define NQ      128
#define NK      6
#define NTOK    2048
#define TPB     256
#define TOKB    8
#define NFEAT   1536
#define FHALF   768

__device__ float g_WcT[D_INF * NQ];      // [i][q]
__device__ float g_W2[NFEAT * D_OUTF];   // [f][d]
__device__ float g_ang[NTOK * NQ];       // [tok][q]

using u64 = unsigned long long;

__device__ __forceinline__ u64 pack2(float x, float y) {
    u64 r; asm("mov.b64 %0, {%1, %2};" : "=l"(r) : "f"(x), "f"(y)); return r;
}
__device__ __forceinline__ u64 fma2(u64 a, u64 b, u64 c) {
    u64 d; asm("fma.rn.f32x2 %0, %1, %2, %3;" : "=l"(d) : "l"(a), "l"(b), "l"(c)); return d;
}
__device__ __forceinline__ float2 unpack2(u64 a) {
    float2 f; asm("mov.b64 {%0, %1}, %2;" : "=f"(f.x), "=f"(f.y) : "l"(a)); return f;
}
__device__ __forceinline__ u64 add2(u64 a, u64 b) {
    u64 d; asm("add.rn.f32x2 %0, %1, %2;" : "=l"(d) : "l"(a), "l"(b)); return d;
}

// ----------------------------------------------------------------------------
// K0: prep. grid 512 x 256.
// ----------------------------------------------------------------------------
__global__ void prep_kernel(const float* __restrict__ Wc_w,
                            const float* __restrict__ A,
                            const float* __restrict__ Bp,
                            float* __restrict__ V) {
    int n = blockIdx.x * blockDim.x + threadIdx.x;
    V[n] = 0.f;                                  // 131072 = NTOK * D_OUTF
    if (n < NFEAT * D_OUTF) {
        int d  = n & (D_OUTF - 1);
        int f  = n >> 6;
        int q  = f & (NQ - 1);
        int kk = f >> 7;                         // 0..11
        int k  = (kk >= NK) ? (kk - NK) : kk;    // 0..5
        int src = (d * NQ + q) * NK + k;
        float a  = A[src];
        float bp = Bp[src];
        float nr = rintf(bp * 0.15915494309189535f);
        float br = fmaf(nr, -6.283185307179586f, bp);
        float sb, cb;
        __sincosf(br, &sb, &cb);
        g_W2[n] = (kk < NK) ? (a * cb) : (a * sb);
    }
    if (n < D_INF * NQ) {
        int q = n & (NQ - 1);
        int i = n >> 7;
        g_WcT[n] = Wc_w[q * D_INF + i];
    }
}

// ----------------------------------------------------------------------------
// K1: angles. grid 256 x 256 (8 tokens per block).
// smem: Xs 8KB | E 8KB  (16KB static)
// ----------------------------------------------------------------------------
__global__ void __launch_bounds__(TPB) angles_kernel(
    const float* __restrict__ X0,
    const float* __restrict__ t,
    const float* __restrict__ Wc_b,
    const float* __restrict__ w) {

    __shared__ float Xs[D_INF * TOKB];     // [256 i][8 tok]
    __shared__ u64   E[4 * 2 * NQ];        // [pair][ih][q]

    const int tid = threadIdx.x;
    const int g0  = blockIdx.x * TOKB;
    const float tb = t[g0 >> 10];

    // load + transpose X
    {
        int tok = tid >> 5;
        int seg = tid & 31;
        const float4* src = (const float4*)(X0 + (size_t)(g0 + tok) * D_INF + seg * 8);
        float4 v0 = src[0];
        float4 v1 = src[1];
        int i0 = seg * 8;
        Xs[(i0 + 0) * TOKB + tok] = v0.x;
        Xs[(i0 + 1) * TOKB + tok] = v0.y;
        Xs[(i0 + 2) * TOKB + tok] = v0.z;
        Xs[(i0 + 3) * TOKB + tok] = v0.w;
        Xs[(i0 + 4) * TOKB + tok] = v1.x;
        Xs[(i0 + 5) * TOKB + tok] = v1.y;
        Xs[(i0 + 6) * TOKB + tok] = v1.z;
        Xs[(i0 + 7) * TOKB + tok] = v1.w;
    }
    __syncthreads();

    // GEMM1: thread = (ih, q), 8 tokens each; i-split halves
    {
        const int ih = tid >> 7;       // 0/1: i in [ih*128, ih*128+128)
        const int q  = tid & (NQ - 1);
        u64 acc[4] = {0ULL, 0ULL, 0ULL, 0ULL};
        #pragma unroll 8
        for (int s = 0; s < D_INF / 2; s++) {
            int i = ih * (D_INF / 2) + s;
            float wv = __ldg(g_WcT + i * NQ + q);
            u64 wd = pack2(wv, wv);
            ulonglong2 xa = *(const ulonglong2*)(Xs + i * TOKB);
            ulonglong2 xb = *(const ulonglong2*)(Xs + i * TOKB + 4);
            acc[0] = fma2(xa.x, wd, acc[0]);
            acc[1] = fma2(xa.y, wd, acc[1]);
            acc[2] = fma2(xb.x, wd, acc[2]);
            acc[3] = fma2(xb.y, wd, acc[3]);
        }
        #pragma unroll
        for (int p = 0; p < 4; p++)
            E[(p * 2 + ih) * NQ + q] = acc[p];
    }
    __syncthreads();

    // reduce halves + bias, write angles
    {
        const int q  = tid & (NQ - 1);
        const int th = tid >> 7;       // tokens th*4 .. th*4+3 (pairs th*2, th*2+1)
        float init = fmaf(w[q], tb, Wc_b[q]);
        u64 bi = pack2(init, init);
        int p0 = th * 2;
        u64 s0 = add2(add2(E[(p0 * 2 + 0) * NQ + q], E[(p0 * 2 + 1) * NQ + q]), bi);
        u64 s1 = add2(add2(E[((p0 + 1) * 2 + 0) * NQ + q], E[((p0 + 1) * 2 + 1) * NQ + q]), bi);
        float2 a01 = unpack2(s0);
        float2 a23 = unpack2(s1);
        float* ap = g_ang + (size_t)(g0 + th * 4) * NQ + q;
        ap[0 * NQ] = a01.x;
        ap[1 * NQ] = a01.y;
        ap[2 * NQ] = a23.x;
        ap[3 * NQ] = a23.y;
    }
}

// ----------------------------------------------------------------------------
// K2: sincos + GEMM2 half. grid 512 = 256 tiles x 2 halves, 256 thr, 4 CTA/SM.
// smem 32KB dynamic: Fs [0,24K) for GEMM2; R [0,32K) aliased for reduction.
// ----------------------------------------------------------------------------
__global__ void __launch_bounds__(TPB, 4) main2_kernel(float* __restrict__ V) {
    extern __shared__ float smem[];
    float* Fs = smem;                  // [768 f_local][8 tok]
    u64*   R  = (u64*)smem;            // [16 k][256] swizzled (aliases Fs after GEMM2)

    const int tid  = threadIdx.x;
    const int tile = blockIdx.x >> 1;
    const int h    = blockIdx.x & 1;   // 0 = sin rows, 1 = cos rows
    const int g0   = tile * TOKB;

    // ---- sincos + harmonic recurrence -> F half -------------------------
    {
        const int q  = tid & (NQ - 1);
        const int th = tid >> 7;        // tokens th*4 .. th*4+3
        const float* ap = g_ang + (size_t)(g0 + th * 4) * NQ + q;
        float ang[4] = {ap[0 * NQ], ap[1 * NQ], ap[2 * NQ], ap[3 * NQ]};

        float sv[4], cv[4], sk[4], ck[4];
        #pragma unroll
        for (int j = 0; j < 4; j++) {
            float nr = rintf(ang[j] * 0.15915494309189535f);
            float ar = fmaf(nr, -6.283185307179586f, ang[j]);
            __sincosf(ar, &sv[j], &cv[j]);
            sk[j] = sv[j]; ck[j] = cv[j];
        }
        float* base = Fs + q * TOKB + th * 4;
        #pragma unroll
        for (int k = 0; k < NK; k++) {
            *(float4*)(base + (k * NQ) * TOKB) =
                h ? make_float4(ck[0], ck[1], ck[2], ck[3])
                  : make_float4(sk[0], sk[1], sk[2], sk[3]);
            #pragma unroll
            for (int j = 0; j < 4; j++) {
                float ns = fmaf(sk[j], cv[j], ck[j] * sv[j]);
                float nc = fmaf(ck[j], cv[j], -sk[j] * sv[j]);
                sk[j] = ns; ck[j] = nc;
            }
        }
    }
    __syncthreads();

    // ---- GEMM2 over 768-feature half, tile 8tok x 4d --------------------
    const int fs = tid >> 4;     // 0..15, f_local = j*16 + fs
    const int dg = tid & 15;     // d = dg*4 + dd
    u64 acc2[16];                // [pair][dd]
    #pragma unroll
    for (int k = 0; k < 16; k++) acc2[k] = 0ULL;

    const float* w2base = g_W2 + (size_t)h * FHALF * D_OUTF + dg * 4;
    #pragma unroll 4
    for (int j = 0; j < FHALF / 16; j++) {
        int fl = j * 16 + fs;
        const float* frow = Fs + fl * TOKB;
        ulonglong2 f01 = *(const ulonglong2*)frow;
        ulonglong2 f23 = *(const ulonglong2*)(frow + 4);
        float4 wv = __ldg((const float4*)(w2base + fl * D_OUTF));
        u64 fp[4] = {f01.x, f01.y, f23.x, f23.y};
        float wa[4] = {wv.x, wv.y, wv.z, wv.w};
        #pragma unroll
        for (int dd = 0; dd < 4; dd++) {
            u64 wd = pack2(wa[dd], wa[dd]);
            #pragma unroll
            for (int p = 0; p < 4; p++)
                acc2[p * 4 + dd] = fma2(fp[p], wd, acc2[p * 4 + dd]);
        }
    }

    // ---- Reduce 16 f-slices (swizzled; R aliases Fs) --------------------
    __syncthreads();
    #pragma unroll
    for (int k = 0; k < 16; k++)
        R[k * 256 + fs * 16 + ((dg + 5 * k) & 15)] = acc2[k];
    __syncthreads();

    {
        int p = tid >> 6;              // token pair 0..3
        int d = tid & 63;
        int k = p * 4 + (d & 3);
        int col = ((d >> 2) + 5 * k) & 15;
        u64 s = 0ULL;
        #pragma unroll
        for (int j = 0; j < 16; j++)
            s = add2(s, R[k * 256 + j * 16 + col]);
        float2 v = unpack2(s);
        float* vp = V + (size_t)(g0 + 2 * p) * D_OUTF + d;
        atomicAdd(vp, v.x);
        atomicAdd(vp + D_OUTF, v.y);
    }
}

// ----------------------------------------------------------------------------
extern "C" void kernel_launch(void* const* d_in, const int* in_sizes, int n_in,
                              void* d_out, int out_size) {
    const float* X0   = (const float*)d_in[0];
    const float* t    = (const float*)d_in[1];
    const float* Wc_w = (const float*)d_in[2];
    const float* Wc_b = (const float*)d_in[3];
    const float* w    = (const float*)d_in[4];
    const float* A    = (const float*)d_in[5];
    const float* Bp   = (const float*)d_in[6];
    float* V = (float*)d_out;

    const int smem2 = 32768;
    cudaFuncSetAttribute(main2_kernel, cudaFuncAttributeMaxDynamicSharedMemorySize, smem2);

    prep_kernel<<<512, 256>>>(Wc_w, A, Bp, V);
    angles_kernel<<<NTOK / TOKB, TPB>>>(X0, t, Wc_b, w);
    main2_kernel<<<2 * NTOK / TOKB, TPB, smem2>>>(V);
}